// round 15
// baseline (speedup 1.0000x reference)
#include <cuda_runtime.h>
#include <cuda_bf16.h>
#include <math.h>
#include <stdint.h>

#define N_NODES 5120
#define TBL 256
#define LATENT 128
#define N_GRAPHS 64
#define N_EDGES 163840
#define NN 80
#define N2 6400
#define HID 12800

#define KU 3328          // padded upper-triangle K for GEMM1 (3240 real + 88 pad)
#define KUR 3240

#define NT 64            // n cols per GEMM block tile
#define KC 64            // k per chunk
#define GT 256           // threads per GEMM block
#define S1 2             // split-K GEMM1 (400 blocks, Kper=1664, 26 chunks)
#define S2 4             // split-K GEMM2 (400 blocks, Kper=3200, 50 chunks)

// smem layout (bytes): double-buffered A (hi+lo) and W (hi+lo)
#define A_STR_B 144
#define W_STR_B 144
#define A_BUF_B 9216                 // 64 rows * 144B, one of hi/lo
#define W_BUF_B 18432                // hi 9216 + lo 9216
#define SM_A 0                       // 2 bufs x (hi + lo) = 36864
#define SM_W 36864                   // 2 bufs x 18432 = 36864
#define SM_TOT 73728

typedef unsigned long long ull;

// ---------------- scratch -----------------------------------------------------
__device__ float g_deg[N_NODES];
__device__ float g_dinv[N_NODES];
__device__ float g_hs[N_NODES * LATENT];
__device__ float g_agg[N_NODES * LATENT];
__device__ __align__(256) __nv_bfloat16 g_Zh[N_GRAPHS * KU];
__device__ __align__(256) __nv_bfloat16 g_Zl[N_GRAPHS * KU];
__device__ __align__(256) __nv_bfloat16 g_H1h[N_GRAPHS * HID];
__device__ __align__(256) __nv_bfloat16 g_H1l[N_GRAPHS * HID];
__device__ float g_P1[S1 * N_GRAPHS * HID];
__device__ float g_P2[S2 * N_GRAPHS * N2];
__device__ int g_t1[KU];
__device__ int g_t2[KU];

// ---------------- helpers -----------------------------------------------------
__device__ __forceinline__ uint32_t smem_u32(const void* p) {
    uint32_t a;
    asm("{ .reg .u64 t; cvta.to.shared.u64 t, %1; cvt.u32.u64 %0, t; }" : "=r"(a) : "l"(p));
    return a;
}
__device__ __forceinline__ void cp_async16(uint32_t dst, const void* src) {
    asm volatile("cp.async.cg.shared.global [%0], [%1], 16;\n" :: "r"(dst), "l"(src));
}
__device__ __forceinline__ void cp_commit() { asm volatile("cp.async.commit_group;\n" ::: "memory"); }
template<int N> __device__ __forceinline__ void cp_wait() {
    asm volatile("cp.async.wait_group %0;\n" :: "n"(N) : "memory");
}
__device__ __forceinline__ void ldsm_x4(uint32_t* r, uint32_t addr) {
    asm volatile("ldmatrix.sync.aligned.m8n8.x4.shared.b16 {%0,%1,%2,%3}, [%4];"
        : "=r"(r[0]), "=r"(r[1]), "=r"(r[2]), "=r"(r[3]) : "r"(addr));
}
__device__ __forceinline__ void ldsm_x4t(uint32_t* r, uint32_t addr) {
    asm volatile("ldmatrix.sync.aligned.m8n8.x4.trans.shared.b16 {%0,%1,%2,%3}, [%4];"
        : "=r"(r[0]), "=r"(r[1]), "=r"(r[2]), "=r"(r[3]) : "r"(addr));
}
__device__ __forceinline__ void mma_bf16(float* c, const uint32_t* a, const uint32_t* b) {
    asm volatile(
        "mma.sync.aligned.m16n8k16.row.col.f32.bf16.bf16.f32 "
        "{%0,%1,%2,%3}, {%4,%5,%6,%7}, {%8,%9}, {%0,%1,%2,%3};\n"
        : "+f"(c[0]), "+f"(c[1]), "+f"(c[2]), "+f"(c[3])
        : "r"(a[0]), "r"(a[1]), "r"(a[2]), "r"(a[3]), "r"(b[0]), "r"(b[1]));
}
__device__ __forceinline__ uint32_t pack_rn(float x, float y) {
    __nv_bfloat162 t = __float22bfloat162_rn(make_float2(x, y));
    return *(uint32_t*)&t;
}
__device__ __forceinline__ void cvt_hilo(float x, __nv_bfloat16& h, __nv_bfloat16& l) {
    h = __float2bfloat16(x);
    l = __float2bfloat16(x - __bfloat162float(h));
}

// ---------------- K1: degree counts + build fold table -----------------------
// (g_deg zero at first call from static init; re-zeroed by k_scatter each run)
__global__ void k_deg(const int* __restrict__ ei) {
    int e = blockIdx.x * 256 + threadIdx.x;
    if (e < N_EDGES) atomicAdd(&g_deg[ei[N_EDGES + e]], 1.0f);
    if (e < KU) {
        if (e >= KUR) { g_t1[e] = 0; g_t2[e] = -1; }
        else {
            int n = 0, start = 0;
            while (start + (NN - n) <= e) { start += NN - n; n++; }
            int m = n + (e - start);
            g_t1[e] = n * NN + m;
            g_t2[e] = (m > n) ? (m * NN + n) : -1;
        }
    }
}

// ---- hs = (x @ Wg) * dinv[row]; emits g_dinv; also zeroes g_agg slice -------
__global__ void k_gemm_h(const float* __restrict__ x, const float* __restrict__ Wg) {
    __shared__ float xs[16][TBL];
    __shared__ float ws[2][16][LATENT];
    int tid = threadIdx.x;
    int col = tid & 127;
    int rh = tid >> 7;
    int rowblk = blockIdx.x * 16;

    {
        int base = (blockIdx.x * 256 + tid) * 8;
        *(float4*)&g_agg[base] = make_float4(0.f, 0.f, 0.f, 0.f);
        *(float4*)&g_agg[base + 4] = make_float4(0.f, 0.f, 0.f, 0.f);
    }

    uint32_t xs_u = smem_u32(&xs[0][0]);
    uint32_t ws_u = smem_u32(&ws[0][0][0]);

#pragma unroll
    for (int i = 0; i < 4; i++) {
        int idx4 = tid + i * 256;
        int r = idx4 >> 6, k4 = idx4 & 63;
        cp_async16(xs_u + (r * TBL + k4 * 4) * 4,
                   x + (size_t)(rowblk + r) * TBL + k4 * 4);
    }
    auto stage_w = [&](int c) {
#pragma unroll
        for (int i = 0; i < 2; i++) {
            int idx4 = tid + i * 256;
            int k = idx4 >> 5, c4 = idx4 & 31;
            cp_async16(ws_u + ((c & 1) * 16 * LATENT + k * LATENT + c4 * 4) * 4,
                       Wg + (size_t)(c * 16 + k) * LATENT + c4 * 4);
        }
        cp_commit();
    };
    stage_w(0);

    float acc[8];
#pragma unroll
    for (int r = 0; r < 8; r++) acc[r] = 0.0f;

#pragma unroll
    for (int c = 0; c < 16; c++) {
        if (c + 1 < 16) { stage_w(c + 1); cp_wait<1>(); }
        else            { cp_wait<0>(); }
        __syncthreads();
#pragma unroll
        for (int k4 = 0; k4 < 4; k4++) {
            float w0 = ws[c & 1][k4 * 4 + 0][col];
            float w1 = ws[c & 1][k4 * 4 + 1][col];
            float w2 = ws[c & 1][k4 * 4 + 2][col];
            float w3 = ws[c & 1][k4 * 4 + 3][col];
#pragma unroll
            for (int r = 0; r < 8; r++) {
                float4 xv = *(const float4*)&xs[rh * 8 + r][c * 16 + k4 * 4];
                acc[r] += xv.x * w0 + xv.y * w1 + xv.z * w2 + xv.w * w3;
            }
        }
        __syncthreads();
    }

#pragma unroll
    for (int r = 0; r < 8; r++) {
        int node = rowblk + rh * 8 + r;
        float d = g_deg[node];
        float di = (d > 0.0f) ? rsqrtf(d) : 0.0f;
        g_hs[node * LATENT + col] = acc[r] * di;
        if (col == 0) g_dinv[node] = di;
    }
}

// ---- scatter; also re-zeroes g_deg for the NEXT replay ----------------------
__global__ void k_scatter(const int* __restrict__ ei) {
    int t = blockIdx.x * 256 + threadIdx.x;
    if (t < N_NODES) g_deg[t] = 0.0f;     // deg already consumed by k_gemm_h
    int e = t >> 5;
    int lane = t & 31;
    if (e < N_EDGES) {
        int s = ei[e];
        int d = ei[N_EDGES + e];
        const float4 v = *(const float4*)&g_hs[s * LATENT + lane * 4];
        atomicAdd((float4*)&g_agg[d * LATENT + lane * 4], v);
    }
}

// ---- z = relu(dinv*agg + bg); upper-tri of z z^T -> hi/lo bf16 --------------
__global__ void k_outer(const float* __restrict__ bg) {
    __shared__ float zs[NN][129];
    int b = blockIdx.x >> 1;
    int half = blockIdx.x & 1;
    int tid = threadIdx.x;

    for (int idx = tid; idx < NN * LATENT; idx += 256) {
        int n = idx >> 7, c = idx & 127;
        int node = b * NN + n;
        float v = g_dinv[node] * g_agg[node * LATENT + c] + bg[c];
        zs[n][c] = (v > 0.0f) ? v : 0.0f;
    }
    __syncthreads();

    int tile = tid >> 1;
    int ksel = tid & 1;
    int tn = half * 8 + (tile >> 4);
    int tm = tile & 15;
    int n0 = tn * 5, m0 = tm * 5;

    float acc[5][5];
#pragma unroll
    for (int i = 0; i < 5; i++)
#pragma unroll
        for (int j = 0; j < 5; j++) acc[i][j] = 0.0f;

#pragma unroll 4
    for (int c2 = 0; c2 < 64; c2++) {
        int c = 2 * c2 + ksel;
        float zn[5], zm[5];
#pragma unroll
        for (int i = 0; i < 5; i++) { zn[i] = zs[n0 + i][c]; zm[i] = zs[m0 + i][c]; }
#pragma unroll
        for (int i = 0; i < 5; i++)
#pragma unroll
            for (int j = 0; j < 5; j++) acc[i][j] += zn[i] * zm[j];
    }

#pragma unroll
    for (int i = 0; i < 5; i++)
#pragma unroll
        for (int j = 0; j < 5; j++)
            acc[i][j] += __shfl_down_sync(0xffffffffu, acc[i][j], 1);

    __nv_bfloat16* oh = &g_Zh[b * KU];
    __nv_bfloat16* ol = &g_Zl[b * KU];
    if (ksel == 0) {
#pragma unroll
        for (int i = 0; i < 5; i++) {
            int n = n0 + i;
            int rowbase = n * NN - (n * (n + 1)) / 2;
#pragma unroll
            for (int j = 0; j < 5; j++) {
                int m = m0 + j;
                if (n <= m) {
                    __nv_bfloat16 h, l;
                    cvt_hilo(acc[i][j], h, l);
                    int t = rowbase + m;
                    oh[t] = h; ol[t] = l;
                }
            }
        }
    }
    if (half == 0 && tid < KU - KUR) {
        oh[KUR + tid] = __float2bfloat16(0.0f);
        ol[KUR + tid] = __float2bfloat16(0.0f);
    }
}

// ---------------- GEMM1: upper-tri A, folded-W, 1 sync/chunk (race-fixed) ----
__global__ void __launch_bounds__(GT, 3)
k_mma1(const float* __restrict__ W) {
    extern __shared__ char smem[];
    const uint32_t sb = smem_u32(smem);
    const int tid = threadIdx.x;
    const int lane = tid & 31;
    const int wid = tid >> 5;

    const int col0 = blockIdx.x * NT;
    const int Kper = KU / S1;              // 1664
    const int kbase = blockIdx.y * Kper;
    const int nch = Kper / KC;             // 26

    const int n4 = tid & 15;
    const int kr0 = tid >> 4;

    auto ldW = [&](int c, float4* w) {
#pragma unroll
        for (int i = 0; i < 4; i++) {
            int t = kbase + c * KC + kr0 + i * 16;
            int r1 = g_t1[t], r2 = g_t2[t];
            float4 a = *(const float4*)(W + (size_t)r1 * HID + col0 + n4 * 4);
            if (r2 >= 0) {
                float4 bb = *(const float4*)(W + (size_t)r2 * HID + col0 + n4 * 4);
                a.x += bb.x; a.y += bb.y; a.z += bb.z; a.w += bb.w;
            }
            w[i] = a;
        }
    };

    float4 wr[4];
    ldW(0, wr);

    const int mstrip = (wid & 3) * 16;
    const int nquad  = (wid >> 2) * 32;
    const int lrow = ((lane >> 3) & 1) * 8 + (lane & 7);
    const int lsel = (lane >> 4) * 8;
    const uint32_t aOff = (uint32_t)(mstrip + lrow) * A_STR_B + lsel * 2;
    const uint32_t wOff = (uint32_t)lrow * W_STR_B + (uint32_t)(nquad + lsel) * 2;

    auto stage_a = [&](int c, int buf) {
        const int kb = kbase + c * KC;
        const uint32_t base = sb + SM_A + (uint32_t)buf * (2 * A_BUF_B);
#pragma unroll
        for (int o = 0; o < 4; o++) {
            int idx = tid + o * GT;
            int sel = idx >> 9;
            int rem = idx & 511;
            int r = rem >> 3, g = rem & 7;
            const __nv_bfloat16* s = (sel ? g_Zl : g_Zh) + (size_t)r * KU + kb + g * 8;
            cp_async16(base + sel * A_BUF_B + r * A_STR_B + g * 16, s);
        }
        cp_commit();
    };

    float acc[4][4];
#pragma unroll
    for (int i = 0; i < 4; i++)
#pragma unroll
        for (int j = 0; j < 4; j++) acc[i][j] = 0.0f;

    stage_a(0, 0);

    for (int c = 0; c < nch; c++) {
        // convert W(c) -> buf c&1 (last reader mma(c-2) sealed by barrier(c-1))
        char* wb = smem + SM_W + (c & 1) * W_BUF_B;
#pragma unroll
        for (int i = 0; i < 4; i++) {
            float4 v = wr[i];
            int krow = kr0 + i * 16;
            uint32_t h01 = pack_rn(v.x, v.y);
            uint32_t h23 = pack_rn(v.z, v.w);
            float l0 = v.x - __uint_as_float(h01 << 16);
            float l1 = v.y - __uint_as_float(h01 & 0xffff0000u);
            float l2 = v.z - __uint_as_float(h23 << 16);
            float l3 = v.w - __uint_as_float(h23 & 0xffff0000u);
            char* ph = wb + krow * W_STR_B + n4 * 8;
            *(uint32_t*)(ph) = h01;  *(uint32_t*)(ph + 4) = h23;
            char* pl = ph + 9216;
            *(uint32_t*)(pl) = pack_rn(l0, l1);
            *(uint32_t*)(pl + 4) = pack_rn(l2, l3);
        }

        cp_wait<0>();            // A(c) complete
        __syncthreads();         // single barrier per chunk

        // stage A(c+1) AFTER barrier: last reader of buf (c+1)&1 was mma(c-1),
        // sealed by this barrier. Prefetch W(c+1) regs too.
        if (c + 1 < nch) { stage_a(c + 1, (c + 1) & 1); ldW(c + 1, wr); }

        const uint32_t aB = sb + SM_A + (uint32_t)(c & 1) * (2 * A_BUF_B);
        const uint32_t wH = sb + SM_W + (uint32_t)(c & 1) * W_BUF_B + wOff;
#pragma unroll
        for (int ks = 0; ks < 4; ks++) {
            uint32_t ah[4], al[4];
            ldsm_x4(ah, aB + aOff + ks * 32);
            ldsm_x4(al, aB + A_BUF_B + aOff + ks * 32);
#pragma unroll
            for (int p = 0; p < 2; p++) {
                uint32_t bh[4], bl[4];
                uint32_t off = (uint32_t)(ks * 16) * W_STR_B + p * 32;
                ldsm_x4t(bh, wH + off);
                ldsm_x4t(bl, wH + 9216 + off);
#pragma unroll
                for (int q = 0; q < 2; q++) {
                    int nf = p * 2 + q;
                    mma_bf16(acc[nf], ah, bh + q * 2);
                    mma_bf16(acc[nf], ah, bl + q * 2);
                    mma_bf16(acc[nf], al, bh + q * 2);
                }
            }
        }
    }

    const int g = lane >> 2, t4 = lane & 3;
    float* P = g_P1 + (size_t)blockIdx.y * N_GRAPHS * HID;
#pragma unroll
    for (int nf = 0; nf < 4; nf++) {
        int n = col0 + nquad + nf * 8 + t4 * 2;
#pragma unroll
        for (int h = 0; h < 2; h++) {
            int m = mstrip + g + h * 8;
            *(float2*)&P[(size_t)m * HID + n] =
                make_float2(acc[nf][h * 2 + 0], acc[nf][h * 2 + 1]);
        }
    }
}

// ---------------- GEMM2: H1 bf16 3-pass, 1 sync/chunk (race-fixed) -----------
__global__ void __launch_bounds__(GT, 3)
k_mma2(const float* __restrict__ W) {
    extern __shared__ char smem[];
    const uint32_t sb = smem_u32(smem);
    const int tid = threadIdx.x;
    const int lane = tid & 31;
    const int wid = tid >> 5;

    const int col0 = blockIdx.x * NT;
    const int Kper = HID / S2;             // 3200
    const int kbase = blockIdx.y * Kper;
    const int nch = Kper / KC;             // 50

    const int n4 = tid & 15;
    const int kr0 = tid >> 4;
    float4 wr[4];
    {
        const float* src = W + (size_t)kbase * N2 + col0 + n4 * 4;
#pragma unroll
        for (int i = 0; i < 4; i++)
            wr[i] = *(const float4*)(src + (size_t)(kr0 + i * 16) * N2);
    }

    const int mstrip = (wid & 3) * 16;
    const int nquad  = (wid >> 2) * 32;
    const int lrow = ((lane >> 3) & 1) * 8 + (lane & 7);
    const int lsel = (lane >> 4) * 8;
    const uint32_t aOff = (uint32_t)(mstrip + lrow) * A_STR_B + lsel * 2;
    const uint32_t wOff = (uint32_t)lrow * W_STR_B + (uint32_t)(nquad + lsel) * 2;

    auto stage_a = [&](int c, int buf) {
        const int kb = kbase + c * KC;
        const uint32_t base = sb + SM_A + (uint32_t)buf * (2 * A_BUF_B);
#pragma unroll
        for (int o = 0; o < 4; o++) {
            int idx = tid + o * GT;
            int sel = idx >> 9;
            int rem = idx & 511;
            int r = rem >> 3, g = rem & 7;
            const __nv_bfloat16* s = (sel ? g_H1l : g_H1h) + (size_t)r * HID + kb + g * 8;
            cp_async16(base + sel * A_BUF_B + r * A_STR_B + g * 16, s);
        }
        cp_commit();
    };

    float acc[4][4];
#pragma unroll
    for (int i = 0; i < 4; i++)
#pragma unroll
        for (int j = 0; j < 4; j++) acc[i][j] = 0.0f;

    stage_a(0, 0);

    for (int c = 0; c < nch; c++) {
        char* wb = smem + SM_W + (c & 1) * W_BUF_B;
#pragma unroll
        for (int i = 0; i < 4; i++) {
            float4 v = wr[i];
            int krow = kr0 + i * 16;
            uint32_t h01 = pack_rn(v.x, v.y);
            uint32_t h23 = pack_rn(v.z, v.w);
            float l0 = v.x - __uint_as_float(h01 << 16);
            float l1 = v.y - __uint_as_float(h01 & 0xffff0000u);
            float l2 = v.z - __uint_as_float(h23 << 16);
            float l3 = v.w - __uint_as_float(h23 & 0xffff0000u);
            char* ph = wb + krow * W_STR_B + n4 * 8;
            *(uint32_t*)(ph) = h01;  *(uint32_t*)(ph + 4) = h23;
            char* pl = ph + 9216;
            *(uint32_t*)(pl) = pack_rn(l0, l1);
            *(uint32_t*)(pl + 4) = pack_rn(l2, l3);
        }

        cp_wait<0>();
        __syncthreads();         // single barrier per chunk

        if (c + 1 < nch) {
            stage_a(c + 1, (c + 1) & 1);
            const float* src = W + (size_t)(kbase + (c + 1) * KC) * N2 + col0 + n4 * 4;
#pragma unroll
            for (int i = 0; i < 4; i++)
                wr[i] = *(const float4*)(src + (size_t)(kr0 + i * 16) * N2);
        }

        const uint32_t aB = sb + SM_A + (uint32_t)(c & 1) * (2 * A_BUF_B);
        const uint32_t wH = sb + SM_W + (uint32_t)(c & 1) * W_BUF_B + wOff;
#pragma unroll
        for (int ks = 0; ks < 4; ks++) {
            uint32_t ah[4], al[4];
            ldsm_x4(ah, aB + aOff + ks * 32);
            ldsm_x4(al, aB + A_BUF_B + aOff + ks * 32);
#pragma unroll
            for (int p = 0; p < 2; p++) {
                uint32_t bh[4], bl[4];
                uint32_t off = (uint32_t)(ks * 16) * W_STR_B + p * 32;
                ldsm_x4t(bh, wH + off);
                ldsm_x4t(bl, wH + 9216 + off);
#pragma unroll
                for (int q = 0; q < 2; q++) {
                    int nf = p * 2 + q;
                    mma_bf16(acc[nf], ah, bh + q * 2);
                    mma_bf16(acc[nf], ah, bl + q * 2);
                    mma_bf16(acc[nf], al, bh + q * 2);
                }
            }
        }
    }

    const int g = lane >> 2, t4 = lane & 3;
    float* P = g_P2 + (size_t)blockIdx.y * N_GRAPHS * N2;
#pragma unroll
    for (int nf = 0; nf < 4; nf++) {
        int n = col0 + nquad + nf * 8 + t4 * 2;
#pragma unroll
        for (int h = 0; h < 2; h++) {
            int m = mstrip + g + h * 8;
            *(float2*)&P[(size_t)m * N2 + n] =
                make_float2(acc[nf][h * 2 + 0], acc[nf][h * 2 + 1]);
        }
    }
}

// ---- combine GEMM1 partials -> bias+relu -> H1 hi/lo ------------------------
__global__ void k_combine1(const float* __restrict__ b1) {
    int i4 = (blockIdx.x * 256 + threadIdx.x) * 4;
    const int TOT = N_GRAPHS * HID;
    float4 v = *(const float4*)&g_P1[i4];
#pragma unroll
    for (int s = 1; s < S1; s++) {
        float4 p = *(const float4*)&g_P1[i4 + s * TOT];
        v.x += p.x; v.y += p.y; v.z += p.z; v.w += p.w;
    }
    int col = i4 - (i4 / HID) * HID;
    float4 b = *(const float4*)&b1[col];
    v.x = fmaxf(v.x + b.x, 0.0f);
    v.y = fmaxf(v.y + b.y, 0.0f);
    v.z = fmaxf(v.z + b.z, 0.0f);
    v.w = fmaxf(v.w + b.w, 0.0f);
    uint32_t h01 = pack_rn(v.x, v.y);
    uint32_t h23 = pack_rn(v.z, v.w);
    float l0 = v.x - __uint_as_float(h01 << 16);
    float l1 = v.y - __uint_as_float(h01 & 0xffff0000u);
    float l2 = v.z - __uint_as_float(h23 << 16);
    float l3 = v.w - __uint_as_float(h23 & 0xffff0000u);
    *(uint2*)&g_H1h[i4] = make_uint2(h01, h23);
    *(uint2*)&g_H1l[i4] = make_uint2(pack_rn(l0, l1), pack_rn(l2, l3));
}

// ---- combine GEMM2 partials -> sigmoid -> out -------------------------------
__global__ void k_combine2(const float* __restrict__ b2, float* __restrict__ out) {
    int i4 = (blockIdx.x * 256 + threadIdx.x) * 4;
    const int TOT = N_GRAPHS * N2;
    float4 v = *(const float4*)&g_P2[i4];
#pragma unroll
    for (int s = 1; s < S2; s++) {
        float4 p = *(const float4*)&g_P2[i4 + s * TOT];
        v.x += p.x; v.y += p.y; v.z += p.z; v.w += p.w;
    }
    int col = i4 - (i4 / N2) * N2;
    float4 b = *(const float4*)&b2[col];
    float4 r;
    r.x = 1.0f / (1.0f + expf(-(v.x + b.x)));
    r.y = 1.0f / (1.0f + expf(-(v.y + b.y)));
    r.z = 1.0f / (1.0f + expf(-(v.z + b.z)));
    r.w = 1.0f / (1.0f + expf(-(v.w + b.w)));
    *(float4*)&out[i4] = r;
}

// ---------------- launch ------------------------------------------------------
extern "C" void kernel_launch(void* const* d_in, const int* in_sizes, int n_in,
                              void* d_out, int out_size) {
    const float* x  = (const float*)d_in[0];
    const int*   ei = (const int*)d_in[1];
    const float* Wg = (const float*)d_in[2];
    const float* bg = (const float*)d_in[3];
    const float* W1 = (const float*)d_in[4];
    const float* b1 = (const float*)d_in[5];
    const float* W2 = (const float*)d_in[6];
    const float* b2 = (const float*)d_in[7];
    float* out = (float*)d_out;

    cudaFuncSetAttribute(k_mma1, cudaFuncAttributeMaxDynamicSharedMemorySize, SM_TOT);
    cudaFuncSetAttribute(k_mma2, cudaFuncAttributeMaxDynamicSharedMemorySize, SM_TOT);

    k_deg<<<(N_EDGES + 255) / 256, 256>>>(ei);
    k_gemm_h<<<N_NODES / 16, 256>>>(x, Wg);
    k_scatter<<<(N_EDGES * 32) / 256, 256>>>(ei);
    k_outer<<<2 * N_GRAPHS, 256>>>(bg);
    // GEMM1: 200 col tiles x S1=2 = 400 blocks, K=3328 (upper-tri folded)
    k_mma1<<<dim3(HID / NT, S1), GT, SM_TOT>>>(W1);
    k_combine1<<<(N_GRAPHS * HID) / 1024, 256>>>(b1);
    // GEMM2: 100 col tiles x S2=4 = 400 blocks, Kper=3200
    k_mma2<<<dim3(N2 / NT, S2), GT, SM_TOT>>>(W2);
    k_combine2<<<(N_GRAPHS * N2) / 1024, 256>>>(b2, out);
}

// round 16
// speedup vs baseline: 1.0401x; 1.0401x over previous
#include <cuda_runtime.h>
#include <cuda_bf16.h>
#include <math.h>
#include <stdint.h>

#define N_NODES 5120
#define TBL 256
#define LATENT 128
#define N_GRAPHS 64
#define N_EDGES 163840
#define NN 80
#define N2 6400
#define HID 12800

#define KU 3264          // padded upper-triangle K for GEMM1 (3240 real + 24 pad)
#define KUR 3240

#define NT 64            // n cols per GEMM block tile
#define KC 64            // k per chunk
#define GT 256           // threads per GEMM block
#define S1 3             // split-K GEMM1 (600 blocks, Kper=1088)
#define S2 4             // split-K GEMM2 (400 blocks, Kper=3200)

// smem layout (bytes)
#define A_STR_B 144
#define W_STR_B 144
#define A_BUF_B 9216                 // 64 rows * 144B, one of hi/lo
#define SM_A 0                       // A: 2 bufs x (hi + lo) = 36864
#define SM_WH 36864
#define SM_WL 46080
#define SM_TOT 55296

typedef unsigned long long ull;

// ---------------- scratch -----------------------------------------------------
__device__ float g_deg[N_NODES];
__device__ float g_dinv[N_NODES];
__device__ float g_hs[N_NODES * LATENT];
__device__ float g_agg[N_NODES * LATENT];
__device__ __align__(256) __nv_bfloat16 g_Zh[N_GRAPHS * KU];
__device__ __align__(256) __nv_bfloat16 g_Zl[N_GRAPHS * KU];
__device__ __align__(256) __nv_bfloat16 g_H1h[N_GRAPHS * HID];
__device__ __align__(256) __nv_bfloat16 g_H1l[N_GRAPHS * HID];
__device__ float g_P1[S1 * N_GRAPHS * HID];
__device__ float g_P2[S2 * N_GRAPHS * N2];
__device__ int g_t1[KU];
__device__ int g_t2[KU];

// ---------------- helpers -----------------------------------------------------
__device__ __forceinline__ uint32_t smem_u32(const void* p) {
    uint32_t a;
    asm("{ .reg .u64 t; cvta.to.shared.u64 t, %1; cvt.u32.u64 %0, t; }" : "=r"(a) : "l"(p));
    return a;
}
__device__ __forceinline__ void cp_async16(uint32_t dst, const void* src) {
    asm volatile("cp.async.cg.shared.global [%0], [%1], 16;\n" :: "r"(dst), "l"(src));
}
__device__ __forceinline__ void cp_commit() { asm volatile("cp.async.commit_group;\n" ::: "memory"); }
template<int N> __device__ __forceinline__ void cp_wait() {
    asm volatile("cp.async.wait_group %0;\n" :: "n"(N) : "memory");
}
__device__ __forceinline__ void ldsm_x4(uint32_t* r, uint32_t addr) {
    asm volatile("ldmatrix.sync.aligned.m8n8.x4.shared.b16 {%0,%1,%2,%3}, [%4];"
        : "=r"(r[0]), "=r"(r[1]), "=r"(r[2]), "=r"(r[3]) : "r"(addr));
}
__device__ __forceinline__ void ldsm_x4t(uint32_t* r, uint32_t addr) {
    asm volatile("ldmatrix.sync.aligned.m8n8.x4.trans.shared.b16 {%0,%1,%2,%3}, [%4];"
        : "=r"(r[0]), "=r"(r[1]), "=r"(r[2]), "=r"(r[3]) : "r"(addr));
}
__device__ __forceinline__ void mma_bf16(float* c, const uint32_t* a, const uint32_t* b) {
    asm volatile(
        "mma.sync.aligned.m16n8k16.row.col.f32.bf16.bf16.f32 "
        "{%0,%1,%2,%3}, {%4,%5,%6,%7}, {%8,%9}, {%0,%1,%2,%3};\n"
        : "+f"(c[0]), "+f"(c[1]), "+f"(c[2]), "+f"(c[3])
        : "r"(a[0]), "r"(a[1]), "r"(a[2]), "r"(a[3]), "r"(b[0]), "r"(b[1]));
}
__device__ __forceinline__ uint32_t pack_rn(float x, float y) {
    __nv_bfloat162 t = __float22bfloat162_rn(make_float2(x, y));
    return *(uint32_t*)&t;
}
__device__ __forceinline__ void cvt_hilo(float x, __nv_bfloat16& h, __nv_bfloat16& l) {
    h = __float2bfloat16(x);
    l = __float2bfloat16(x - __bfloat162float(h));
}

// ---------------- K1: degree counts + build fold table -----------------------
// (g_deg zero at first call from static init; re-zeroed by k_scatter each run)
__global__ void k_deg(const int* __restrict__ ei) {
    int e = blockIdx.x * 256 + threadIdx.x;
    if (e < N_EDGES) atomicAdd(&g_deg[ei[N_EDGES + e]], 1.0f);
    if (e < KU) {
        if (e >= KUR) { g_t1[e] = 0; g_t2[e] = -1; }
        else {
            int n = 0, start = 0;
            while (start + (NN - n) <= e) { start += NN - n; n++; }
            int m = n + (e - start);
            g_t1[e] = n * NN + m;
            g_t2[e] = (m > n) ? (m * NN + n) : -1;
        }
    }
}

// ---- hs = (x @ Wg) * dinv[row]; emits g_dinv; also zeroes g_agg slice -------
__global__ void k_gemm_h(const float* __restrict__ x, const float* __restrict__ Wg) {
    __shared__ float xs[16][TBL];
    __shared__ float ws[2][16][LATENT];
    int tid = threadIdx.x;
    int col = tid & 127;
    int rh = tid >> 7;
    int rowblk = blockIdx.x * 16;

    {
        int base = (blockIdx.x * 256 + tid) * 8;
        *(float4*)&g_agg[base] = make_float4(0.f, 0.f, 0.f, 0.f);
        *(float4*)&g_agg[base + 4] = make_float4(0.f, 0.f, 0.f, 0.f);
    }

    uint32_t xs_u = smem_u32(&xs[0][0]);
    uint32_t ws_u = smem_u32(&ws[0][0][0]);

#pragma unroll
    for (int i = 0; i < 4; i++) {
        int idx4 = tid + i * 256;
        int r = idx4 >> 6, k4 = idx4 & 63;
        cp_async16(xs_u + (r * TBL + k4 * 4) * 4,
                   x + (size_t)(rowblk + r) * TBL + k4 * 4);
    }
    auto stage_w = [&](int c) {
#pragma unroll
        for (int i = 0; i < 2; i++) {
            int idx4 = tid + i * 256;
            int k = idx4 >> 5, c4 = idx4 & 31;
            cp_async16(ws_u + ((c & 1) * 16 * LATENT + k * LATENT + c4 * 4) * 4,
                       Wg + (size_t)(c * 16 + k) * LATENT + c4 * 4);
        }
        cp_commit();
    };
    stage_w(0);

    float acc[8];
#pragma unroll
    for (int r = 0; r < 8; r++) acc[r] = 0.0f;

#pragma unroll
    for (int c = 0; c < 16; c++) {
        if (c + 1 < 16) { stage_w(c + 1); cp_wait<1>(); }
        else            { cp_wait<0>(); }
        __syncthreads();
#pragma unroll
        for (int k4 = 0; k4 < 4; k4++) {
            float w0 = ws[c & 1][k4 * 4 + 0][col];
            float w1 = ws[c & 1][k4 * 4 + 1][col];
            float w2 = ws[c & 1][k4 * 4 + 2][col];
            float w3 = ws[c & 1][k4 * 4 + 3][col];
#pragma unroll
            for (int r = 0; r < 8; r++) {
                float4 xv = *(const float4*)&xs[rh * 8 + r][c * 16 + k4 * 4];
                acc[r] += xv.x * w0 + xv.y * w1 + xv.z * w2 + xv.w * w3;
            }
        }
        __syncthreads();
    }

#pragma unroll
    for (int r = 0; r < 8; r++) {
        int node = rowblk + rh * 8 + r;
        float d = g_deg[node];
        float di = (d > 0.0f) ? rsqrtf(d) : 0.0f;
        g_hs[node * LATENT + col] = acc[r] * di;
        if (col == 0) g_dinv[node] = di;
    }
}

// ---- scatter; also re-zeroes g_deg for the NEXT replay ----------------------
__global__ void k_scatter(const int* __restrict__ ei) {
    int t = blockIdx.x * 256 + threadIdx.x;
    if (t < N_NODES) g_deg[t] = 0.0f;     // deg already consumed by k_gemm_h
    int e = t >> 5;
    int lane = t & 31;
    if (e < N_EDGES) {
        int s = ei[e];
        int d = ei[N_EDGES + e];
        const float4 v = *(const float4*)&g_hs[s * LATENT + lane * 4];
        atomicAdd((float4*)&g_agg[d * LATENT + lane * 4], v);
    }
}

// ---- z = relu(dinv*agg + bg); upper-tri of z z^T -> hi/lo bf16 --------------
// 256 blocks (4 per graph). 4 lanes per tile split LATENT; shfl reduce.
__global__ void k_outer(const float* __restrict__ bg) {
    __shared__ float zs[NN][129];
    int b = blockIdx.x >> 2;
    int quarter = blockIdx.x & 3;
    int tid = threadIdx.x;

    for (int idx = tid; idx < NN * LATENT; idx += 256) {
        int n = idx >> 7, c = idx & 127;
        int node = b * NN + n;
        float v = g_dinv[node] * g_agg[node * LATENT + c] + bg[c];
        zs[n][c] = (v > 0.0f) ? v : 0.0f;
    }
    __syncthreads();

    int tile = tid >> 2;               // 0..63
    int ksel = tid & 3;                // 4-way k split
    int tn = quarter * 4 + (tile >> 4);  // 0..15
    int tm = tile & 15;
    int n0 = tn * 5, m0 = tm * 5;

    float acc[5][5];
#pragma unroll
    for (int i = 0; i < 5; i++)
#pragma unroll
        for (int j = 0; j < 5; j++) acc[i][j] = 0.0f;

#pragma unroll 4
    for (int c4 = 0; c4 < 32; c4++) {
        int c = 4 * c4 + ksel;
        float zn[5], zm[5];
#pragma unroll
        for (int i = 0; i < 5; i++) { zn[i] = zs[n0 + i][c]; zm[i] = zs[m0 + i][c]; }
#pragma unroll
        for (int i = 0; i < 5; i++)
#pragma unroll
            for (int j = 0; j < 5; j++) acc[i][j] += zn[i] * zm[j];
    }

    // 4-lane reduce onto ksel==0
#pragma unroll
    for (int i = 0; i < 5; i++)
#pragma unroll
        for (int j = 0; j < 5; j++) {
            acc[i][j] += __shfl_down_sync(0xffffffffu, acc[i][j], 2);
            acc[i][j] += __shfl_down_sync(0xffffffffu, acc[i][j], 1);
        }

    __nv_bfloat16* oh = &g_Zh[b * KU];
    __nv_bfloat16* ol = &g_Zl[b * KU];
    if (ksel == 0) {
#pragma unroll
        for (int i = 0; i < 5; i++) {
            int n = n0 + i;
            int rowbase = n * NN - (n * (n + 1)) / 2;
#pragma unroll
            for (int j = 0; j < 5; j++) {
                int m = m0 + j;
                if (n <= m) {
                    __nv_bfloat16 h, l;
                    cvt_hilo(acc[i][j], h, l);
                    int t = rowbase + m;
                    oh[t] = h; ol[t] = l;
                }
            }
        }
    }
    if (quarter == 0 && tid < KU - KUR) {
        oh[KUR + tid] = __float2bfloat16(0.0f);
        ol[KUR + tid] = __float2bfloat16(0.0f);
    }
}

// ---------------- GEMM1: upper-tri A, folded-W bf16 3-pass (round-13 form) ---
__global__ void __launch_bounds__(GT, 2)
k_mma1(const float* __restrict__ W) {
    extern __shared__ char smem[];
    const uint32_t sb = smem_u32(smem);
    const int tid = threadIdx.x;
    const int lane = tid & 31;
    const int wid = tid >> 5;

    const int col0 = blockIdx.x * NT;
    const int Kper = KU / S1;
    const int kbase = blockIdx.y * Kper;
    const int nch = Kper / KC;

    const int n4 = tid & 15;
    const int kr0 = tid >> 4;

    auto ldW = [&](int c, float4* w) {
#pragma unroll
        for (int i = 0; i < 4; i++) {
            int t = kbase + c * KC + kr0 + i * 16;
            int r1 = g_t1[t], r2 = g_t2[t];
            float4 a = *(const float4*)(W + (size_t)r1 * HID + col0 + n4 * 4);
            if (r2 >= 0) {
                float4 bb = *(const float4*)(W + (size_t)r2 * HID + col0 + n4 * 4);
                a.x += bb.x; a.y += bb.y; a.z += bb.z; a.w += bb.w;
            }
            w[i] = a;
        }
    };

    float4 wr[4];
    ldW(0, wr);

    const int mstrip = (wid & 3) * 16;
    const int nquad  = (wid >> 2) * 32;
    const int lrow = ((lane >> 3) & 1) * 8 + (lane & 7);
    const int lsel = (lane >> 4) * 8;
    const uint32_t aOff = (uint32_t)(mstrip + lrow) * A_STR_B + lsel * 2;
    const uint32_t wH = sb + SM_WH + (uint32_t)lrow * W_STR_B + (uint32_t)(nquad + lsel) * 2;
    const uint32_t wL = sb + SM_WL + (uint32_t)lrow * W_STR_B + (uint32_t)(nquad + lsel) * 2;

    auto stage_a = [&](int c, int buf) {
        const int kb = kbase + c * KC;
        const uint32_t base = sb + SM_A + (uint32_t)buf * (2 * A_BUF_B);
#pragma unroll
        for (int o = 0; o < 4; o++) {
            int idx = tid + o * GT;
            int sel = idx >> 9;
            int rem = idx & 511;
            int r = rem >> 3, g = rem & 7;
            const __nv_bfloat16* s = (sel ? g_Zl : g_Zh) + (size_t)r * KU + kb + g * 8;
            cp_async16(base + sel * A_BUF_B + r * A_STR_B + g * 16, s);
        }
        cp_commit();
    };

    float acc[4][4];
#pragma unroll
    for (int i = 0; i < 4; i++)
#pragma unroll
        for (int j = 0; j < 4; j++) acc[i][j] = 0.0f;

    stage_a(0, 0);

    for (int c = 0; c < nch; c++) {
        if (c + 1 < nch) stage_a(c + 1, (c + 1) & 1);

#pragma unroll
        for (int i = 0; i < 4; i++) {
            float4 v = wr[i];
            int krow = kr0 + i * 16;
            uint32_t h01 = pack_rn(v.x, v.y);
            uint32_t h23 = pack_rn(v.z, v.w);
            float l0 = v.x - __uint_as_float(h01 << 16);
            float l1 = v.y - __uint_as_float(h01 & 0xffff0000u);
            float l2 = v.z - __uint_as_float(h23 << 16);
            float l3 = v.w - __uint_as_float(h23 & 0xffff0000u);
            char* ph = smem + SM_WH + krow * W_STR_B + n4 * 8;
            char* pl = smem + SM_WL + krow * W_STR_B + n4 * 8;
            *(uint32_t*)(ph) = h01;  *(uint32_t*)(ph + 4) = h23;
            *(uint32_t*)(pl) = pack_rn(l0, l1);
            *(uint32_t*)(pl + 4) = pack_rn(l2, l3);
        }

        if (c + 1 < nch) cp_wait<1>();
        else             cp_wait<0>();
        __syncthreads();

        if (c + 1 < nch) ldW(c + 1, wr);

        const uint32_t aB = sb + SM_A + (uint32_t)(c & 1) * (2 * A_BUF_B);
#pragma unroll
        for (int ks = 0; ks < 4; ks++) {
            uint32_t ah[4], al[4];
            ldsm_x4(ah, aB + aOff + ks * 32);
            ldsm_x4(al, aB + A_BUF_B + aOff + ks * 32);
#pragma unroll
            for (int p = 0; p < 2; p++) {
                uint32_t bh[4], bl[4];
                uint32_t off = (uint32_t)(ks * 16) * W_STR_B + p * 32;
                ldsm_x4t(bh, wH + off);
                ldsm_x4t(bl, wL + off);
#pragma unroll
                for (int q = 0; q < 2; q++) {
                    int nf = p * 2 + q;
                    mma_bf16(acc[nf], ah, bh + q * 2);
                    mma_bf16(acc[nf], ah, bl + q * 2);
                    mma_bf16(acc[nf], al, bh + q * 2);
                }
            }
        }
        __syncthreads();
    }

    const int g = lane >> 2, t4 = lane & 3;
    float* P = g_P1 + (size_t)blockIdx.y * N_GRAPHS * HID;
#pragma unroll
    for (int nf = 0; nf < 4; nf++) {
        int n = col0 + nquad + nf * 8 + t4 * 2;
#pragma unroll
        for (int h = 0; h < 2; h++) {
            int m = mstrip + g + h * 8;
            *(float2*)&P[(size_t)m * HID + n] =
                make_float2(acc[nf][h * 2 + 0], acc[nf][h * 2 + 1]);
        }
    }
}

// ---------------- GEMM2: H1 bf16 3-pass (round-13 form) ----------------------
__global__ void __launch_bounds__(GT, 3)
k_mma2(const float* __restrict__ W) {
    extern __shared__ char smem[];
    const uint32_t sb = smem_u32(smem);
    const int tid = threadIdx.x;
    const int lane = tid & 31;
    const int wid = tid >> 5;

    const int col0 = blockIdx.x * NT;
    const int Kper = HID / S2;             // 3200
    const int kbase = blockIdx.y * Kper;
    const int nch = Kper / KC;             // 50

    const int n4 = tid & 15;
    const int kr0 = tid >> 4;
    float4 wr[4];
    {
        const float* src = W + (size_t)kbase * N2 + col0 + n4 * 4;
#pragma unroll
        for (int i = 0; i < 4; i++)
            wr[i] = *(const float4*)(src + (size_t)(kr0 + i * 16) * N2);
    }

    const int mstrip = (wid & 3) * 16;
    const int nquad  = (wid >> 2) * 32;
    const int lrow = ((lane >> 3) & 1) * 8 + (lane & 7);
    const int lsel = (lane >> 4) * 8;
    const uint32_t aOff = (uint32_t)(mstrip + lrow) * A_STR_B + lsel * 2;
    const uint32_t wH = sb + SM_WH + (uint32_t)lrow * W_STR_B + (uint32_t)(nquad + lsel) * 2;
    const uint32_t wL = sb + SM_WL + (uint32_t)lrow * W_STR_B + (uint32_t)(nquad + lsel) * 2;

    auto stage_a = [&](int c, int buf) {
        const int kb = kbase + c * KC;
        const uint32_t base = sb + SM_A + (uint32_t)buf * (2 * A_BUF_B);
#pragma unroll
        for (int o = 0; o < 4; o++) {
            int idx = tid + o * GT;
            int sel = idx >> 9;
            int rem = idx & 511;
            int r = rem >> 3, g = rem & 7;
            const __nv_bfloat16* s = (sel ? g_H1l : g_H1h) + (size_t)r * HID + kb + g * 8;
            cp_async16(base + sel * A_BUF_B + r * A_STR_B + g * 16, s);
        }
        cp_commit();
    };

    float acc[4][4];
#pragma unroll
    for (int i = 0; i < 4; i++)
#pragma unroll
        for (int j = 0; j < 4; j++) acc[i][j] = 0.0f;

    stage_a(0, 0);

    for (int c = 0; c < nch; c++) {
        if (c + 1 < nch) stage_a(c + 1, (c + 1) & 1);

#pragma unroll
        for (int i = 0; i < 4; i++) {
            float4 v = wr[i];
            int krow = kr0 + i * 16;
            uint32_t h01 = pack_rn(v.x, v.y);
            uint32_t h23 = pack_rn(v.z, v.w);
            float l0 = v.x - __uint_as_float(h01 << 16);
            float l1 = v.y - __uint_as_float(h01 & 0xffff0000u);
            float l2 = v.z - __uint_as_float(h23 << 16);
            float l3 = v.w - __uint_as_float(h23 & 0xffff0000u);
            char* ph = smem + SM_WH + krow * W_STR_B + n4 * 8;
            char* pl = smem + SM_WL + krow * W_STR_B + n4 * 8;
            *(uint32_t*)(ph) = h01;  *(uint32_t*)(ph + 4) = h23;
            *(uint32_t*)(pl) = pack_rn(l0, l1);
            *(uint32_t*)(pl + 4) = pack_rn(l2, l3);
        }

        if (c + 1 < nch) cp_wait<1>();
        else             cp_wait<0>();
        __syncthreads();

        if (c + 1 < nch) {
            const float* src = W + (size_t)(kbase + (c + 1) * KC) * N2 + col0 + n4 * 4;
#pragma unroll
            for (int i = 0; i < 4; i++)
                wr[i] = *(const float4*)(src + (size_t)(kr0 + i * 16) * N2);
        }

        const uint32_t aB = sb + SM_A + (uint32_t)(c & 1) * (2 * A_BUF_B);
#pragma unroll
        for (int ks = 0; ks < 4; ks++) {
            uint32_t ah[4], al[4];
            ldsm_x4(ah, aB + aOff + ks * 32);
            ldsm_x4(al, aB + A_BUF_B + aOff + ks * 32);
#pragma unroll
            for (int p = 0; p < 2; p++) {
                uint32_t bh[4], bl[4];
                uint32_t off = (uint32_t)(ks * 16) * W_STR_B + p * 32;
                ldsm_x4t(bh, wH + off);
                ldsm_x4t(bl, wL + off);
#pragma unroll
                for (int q = 0; q < 2; q++) {
                    int nf = p * 2 + q;
                    mma_bf16(acc[nf], ah, bh + q * 2);
                    mma_bf16(acc[nf], ah, bl + q * 2);
                    mma_bf16(acc[nf], al, bh + q * 2);
                }
            }
        }
        __syncthreads();
    }

    const int g = lane >> 2, t4 = lane & 3;
    float* P = g_P2 + (size_t)blockIdx.y * N_GRAPHS * N2;
#pragma unroll
    for (int nf = 0; nf < 4; nf++) {
        int n = col0 + nquad + nf * 8 + t4 * 2;
#pragma unroll
        for (int h = 0; h < 2; h++) {
            int m = mstrip + g + h * 8;
            *(float2*)&P[(size_t)m * N2 + n] =
                make_float2(acc[nf][h * 2 + 0], acc[nf][h * 2 + 1]);
        }
    }
}

// ---- combine GEMM1 partials -> bias+relu -> H1 hi/lo ------------------------
__global__ void k_combine1(const float* __restrict__ b1) {
    int i4 = (blockIdx.x * 256 + threadIdx.x) * 4;
    const int TOT = N_GRAPHS * HID;
    float4 v = *(const float4*)&g_P1[i4];
#pragma unroll
    for (int s = 1; s < S1; s++) {
        float4 p = *(const float4*)&g_P1[i4 + s * TOT];
        v.x += p.x; v.y += p.y; v.z += p.z; v.w += p.w;
    }
    int col = i4 - (i4 / HID) * HID;
    float4 b = *(const float4*)&b1[col];
    v.x = fmaxf(v.x + b.x, 0.0f);
    v.y = fmaxf(v.y + b.y, 0.0f);
    v.z = fmaxf(v.z + b.z, 0.0f);
    v.w = fmaxf(v.w + b.w, 0.0f);
    uint32_t h01 = pack_rn(v.x, v.y);
    uint32_t h23 = pack_rn(v.z, v.w);
    float l0 = v.x - __uint_as_float(h01 << 16);
    float l1 = v.y - __uint_as_float(h01 & 0xffff0000u);
    float l2 = v.z - __uint_as_float(h23 << 16);
    float l3 = v.w - __uint_as_float(h23 & 0xffff0000u);
    *(uint2*)&g_H1h[i4] = make_uint2(h01, h23);
    *(uint2*)&g_H1l[i4] = make_uint2(pack_rn(l0, l1), pack_rn(l2, l3));
}

// ---- combine GEMM2 partials -> sigmoid -> out -------------------------------
__global__ void k_combine2(const float* __restrict__ b2, float* __restrict__ out) {
    int i4 = (blockIdx.x * 256 + threadIdx.x) * 4;
    const int TOT = N_GRAPHS * N2;
    float4 v = *(const float4*)&g_P2[i4];
#pragma unroll
    for (int s = 1; s < S2; s++) {
        float4 p = *(const float4*)&g_P2[i4 + s * TOT];
        v.x += p.x; v.y += p.y; v.z += p.z; v.w += p.w;
    }
    int col = i4 - (i4 / N2) * N2;
    float4 b = *(const float4*)&b2[col];
    float4 r;
    r.x = 1.0f / (1.0f + expf(-(v.x + b.x)));
    r.y = 1.0f / (1.0f + expf(-(v.y + b.y)));
    r.z = 1.0f / (1.0f + expf(-(v.z + b.z)));
    r.w = 1.0f / (1.0f + expf(-(v.w + b.w)));
    *(float4*)&out[i4] = r;
}

// ---------------- launch ------------------------------------------------------
extern "C" void kernel_launch(void* const* d_in, const int* in_sizes, int n_in,
                              void* d_out, int out_size) {
    const float* x  = (const float*)d_in[0];
    const int*   ei = (const int*)d_in[1];
    const float* Wg = (const float*)d_in[2];
    const float* bg = (const float*)d_in[3];
    const float* W1 = (const float*)d_in[4];
    const float* b1 = (const float*)d_in[5];
    const float* W2 = (const float*)d_in[6];
    const float* b2 = (const float*)d_in[7];
    float* out = (float*)d_out;

    cudaFuncSetAttribute(k_mma1, cudaFuncAttributeMaxDynamicSharedMemorySize, SM_TOT);
    cudaFuncSetAttribute(k_mma2, cudaFuncAttributeMaxDynamicSharedMemorySize, SM_TOT);

    k_deg<<<(N_EDGES + 255) / 256, 256>>>(ei);
    k_gemm_h<<<N_NODES / 16, 256>>>(x, Wg);
    k_scatter<<<(N_EDGES * 32) / 256, 256>>>(ei);
    k_outer<<<4 * N_GRAPHS, 256>>>(bg);
    // GEMM1: 200 col tiles x S1=3 = 600 blocks, K=3264 (upper-tri folded)
    k_mma1<<<dim3(HID / NT, S1), GT, SM_TOT>>>(W1);
    k_combine1<<<(N_GRAPHS * HID) / 1024, 256>>>(b1);
    // GEMM2: 100 col tiles x S2=4 = 400 blocks, Kper=3200
    k_mma2<<<dim3(N2 / NT, S2), GT, SM_TOT>>>(W2);
    k_combine2<<<(N_GRAPHS * N2) / 1024, 256>>>(b2, out);
}